// round 3
// baseline (speedup 1.0000x reference)
#include <cuda_runtime.h>
#include <math.h>

// ---------------- problem constants ----------------
namespace {
constexpr int B  = 2;
constexpr int S  = 2048;
constexpr int D  = 512;
constexpr int H  = 8;
constexpr int DK = 64;
constexpr int NB = B * S;     // 4096 tokens
constexpr int BH = B * H;     // 16 (b,h) pairs
constexpr int DH = D / 2;     // 256 gate hidden
constexpr float DECAY = 0.02f;
constexpr float LN_EPS = 1e-5f;
}

// ---------------- device scratch (no allocations allowed) ----------------
__device__ float g_q[BH * S * DK];      // (b,h,s,dk)
__device__ float g_k[BH * S * DK];
__device__ float g_v[BH * S * DK];
__device__ float g_o[BH * S * DK];
__device__ float g_proj[NB * D];
__device__ float g_hidden[NB * DH];
__device__ float g_gate[NB];
__device__ float g_rowsum[BH * S];
__device__ float g_decay[S];

// ---------------- init: zero rowsums, build decay table ----------------
__global__ void init_kernel() {
    int idx = blockIdx.x * blockDim.x + threadIdx.x;
    if (idx < BH * S) g_rowsum[idx] = 0.0f;
    if (idx < S)      g_decay[idx] = expf(-DECAY * (float)idx);
}

// ---------------- QKV projection GEMM ----------------
// C(4096 x 512) = x @ W + b, written into (b,h,s,dk) layout.
// 128x128 tile, BK=8, 256 threads, 8x8 microtile.
__global__ __launch_bounds__(256) void qkv_kernel(
    const float* __restrict__ x,
    const float* __restrict__ wq, const float* __restrict__ bq,
    const float* __restrict__ wk, const float* __restrict__ bk,
    const float* __restrict__ wv, const float* __restrict__ bv)
{
    __shared__ __align__(16) float As[8][128];
    __shared__ __align__(16) float Bs[8][128];

    const float* W; const float* bias; float* out;
    if (blockIdx.z == 0)      { W = wq; bias = bq; out = g_q; }
    else if (blockIdx.z == 1) { W = wk; bias = bk; out = g_k; }
    else                      { W = wv; bias = bv; out = g_v; }

    const int row0 = blockIdx.y * 128;
    const int col0 = blockIdx.x * 128;
    const int tid = threadIdx.x;
    const int tx = tid & 15, ty = tid >> 4;

    float acc[8][8] = {};

    for (int k0 = 0; k0 < D; k0 += 8) {
        {
            int r = tid >> 1, kk = (tid & 1) * 4;
            float4 a = *(const float4*)&x[(row0 + r) * D + k0 + kk];
            As[kk + 0][r] = a.x; As[kk + 1][r] = a.y;
            As[kk + 2][r] = a.z; As[kk + 3][r] = a.w;
        }
        {
            int kk = tid >> 5, c = (tid & 31) * 4;
            *(float4*)&Bs[kk][c] = *(const float4*)&W[(k0 + kk) * D + col0 + c];
        }
        __syncthreads();
        #pragma unroll
        for (int kk = 0; kk < 8; kk++) {
            float a[8], b[8];
            *(float4*)&a[0] = *(float4*)&As[kk][ty * 8];
            *(float4*)&a[4] = *(float4*)&As[kk][ty * 8 + 4];
            *(float4*)&b[0] = *(float4*)&Bs[kk][tx * 8];
            *(float4*)&b[4] = *(float4*)&Bs[kk][tx * 8 + 4];
            #pragma unroll
            for (int i = 0; i < 8; i++)
                #pragma unroll
                for (int j = 0; j < 8; j++)
                    acc[i][j] += a[i] * b[j];
        }
        __syncthreads();
    }

    // epilogue: +bias, write to (b,h,s,dk)
    #pragma unroll
    for (int i = 0; i < 8; i++) {
        int n = row0 + ty * 8 + i;
        int b = n >> 11, s = n & (S - 1);
        int d0 = col0 + tx * 8;          // 8 consecutive d, never crosses a 64-block
        int h = d0 >> 6, dk = d0 & 63;
        float v[8];
        #pragma unroll
        for (int j = 0; j < 8; j++) v[j] = acc[i][j] + bias[d0 + j];
        float* dst = &out[((b * H + h) * S + s) * DK + dk];
        *(float4*)&dst[0] = *(float4*)&v[0];
        *(float4*)&dst[4] = *(float4*)&v[4];
    }
}

// ---------------- scores: P = exp(QK^T/8 + bias), rowsum via atomics ----------------
// One block = 128q x 128k tile for one (b,h). DK=64 loaded in one shot.
// Dynamic smem: Qs[64][128] + Ks[64][128] + ssum[128] = 66048 B.
__global__ __launch_bounds__(256) void scores_kernel(float* __restrict__ attn)
{
    extern __shared__ __align__(16) float sm[];
    float (*Qs)[128] = (float(*)[128])sm;
    float (*Ks)[128] = (float(*)[128])(sm + 64 * 128);
    float* ssum = sm + 2 * 64 * 128;

    const int bh = blockIdx.z;
    const int row0 = blockIdx.y * 128;   // query index i
    const int col0 = blockIdx.x * 128;   // key index j
    const int tid = threadIdx.x;
    const int tx = tid & 15, ty = tid >> 4;

    const float* qb = g_q + bh * S * DK;
    const float* kb = g_k + bh * S * DK;

    #pragma unroll
    for (int i = 0; i < 8; i++) {
        int lin = i * 256 + tid;          // float4 units, 2048 total
        int r = lin >> 4, kk = (lin & 15) * 4;
        float4 a = *(const float4*)&qb[(row0 + r) * DK + kk];
        Qs[kk + 0][r] = a.x; Qs[kk + 1][r] = a.y;
        Qs[kk + 2][r] = a.z; Qs[kk + 3][r] = a.w;
    }
    #pragma unroll
    for (int i = 0; i < 8; i++) {
        int lin = i * 256 + tid;
        int c = lin >> 4, kk = (lin & 15) * 4;
        float4 a = *(const float4*)&kb[(col0 + c) * DK + kk];
        Ks[kk + 0][c] = a.x; Ks[kk + 1][c] = a.y;
        Ks[kk + 2][c] = a.z; Ks[kk + 3][c] = a.w;
    }
    if (tid < 128) ssum[tid] = 0.0f;
    __syncthreads();

    float acc[8][8] = {};
    #pragma unroll 16
    for (int kk = 0; kk < 64; kk++) {
        float a[8], b[8];
        *(float4*)&a[0] = *(float4*)&Qs[kk][ty * 8];
        *(float4*)&a[4] = *(float4*)&Qs[kk][ty * 8 + 4];
        *(float4*)&b[0] = *(float4*)&Ks[kk][tx * 8];
        *(float4*)&b[4] = *(float4*)&Ks[kk][tx * 8 + 4];
        #pragma unroll
        for (int i = 0; i < 8; i++)
            #pragma unroll
            for (int j = 0; j < 8; j++)
                acc[i][j] += a[i] * b[j];
    }

    float rsum[8] = {};
    #pragma unroll
    for (int i = 0; i < 8; i++) {
        int gi = row0 + ty * 8 + i;
        float p[8];
        #pragma unroll
        for (int j = 0; j < 8; j++) {
            int gj = col0 + tx * 8 + j;
            float v = acc[i][j] * 0.125f;
            int dist = gi - gj;
            if (dist >= 0) v += g_decay[dist];
            p[j] = __expf(v);
            rsum[i] += p[j];
        }
        float* arow = attn + ((long)(bh * S + gi)) * S + col0 + tx * 8;
        *(float4*)&arow[0] = *(float4*)&p[0];
        *(float4*)&arow[4] = *(float4*)&p[4];
    }
    #pragma unroll
    for (int i = 0; i < 8; i++) atomicAdd(&ssum[ty * 8 + i], rsum[i]);
    __syncthreads();
    if (tid < 128) atomicAdd(&g_rowsum[bh * S + row0 + tid], ssum[tid]);
}

// ---------------- attn@V + in-place normalization of attn ----------------
// One block = 64 q-rows x 64 v-cols (full DK) for one (b,h); loops k in 64-chunks.
// While loading each P tile: scale by 1/rowsum, write normalized attn back.
__global__ __launch_bounds__(256) void attnv_kernel(float* __restrict__ attn)
{
    __shared__ __align__(16) float Ps[64][64];
    __shared__ __align__(16) float Vs[64][64];
    __shared__ float srow[64];

    const int bh = blockIdx.y;
    const int row0 = blockIdx.x * 64;
    const int tid = threadIdx.x;
    const int tx = tid & 15, ty = tid >> 4;

    if (tid < 64) srow[tid] = 1.0f / g_rowsum[bh * S + row0 + tid];
    __syncthreads();

    float acc[4][4] = {};

    for (int k0 = 0; k0 < S; k0 += 64) {
        #pragma unroll
        for (int i = 0; i < 4; i++) {
            int lin = i * 256 + tid;       // 1024 float4 units = 4096 floats
            int r = lin >> 4, kk = (lin & 15) * 4;
            float* gp = attn + ((long)(bh * S + row0 + r)) * S + k0 + kk;
            float4 a = *(const float4*)gp;
            float inv = srow[r];
            a.x *= inv; a.y *= inv; a.z *= inv; a.w *= inv;
            *(float4*)gp = a;              // normalized attn written back
            Ps[kk + 0][r] = a.x; Ps[kk + 1][r] = a.y;
            Ps[kk + 2][r] = a.z; Ps[kk + 3][r] = a.w;
        }
        #pragma unroll
        for (int i = 0; i < 4; i++) {
            int lin = i * 256 + tid;
            int kk = lin >> 4, c = (lin & 15) * 4;
            *(float4*)&Vs[kk][c] =
                *(const float4*)&g_v[(bh * S + k0 + kk) * DK + c];
        }
        __syncthreads();
        #pragma unroll 16
        for (int kk = 0; kk < 64; kk++) {
            float a[4], b[4];
            *(float4*)&a[0] = *(float4*)&Ps[kk][ty * 4];
            *(float4*)&b[0] = *(float4*)&Vs[kk][tx * 4];
            #pragma unroll
            for (int i = 0; i < 4; i++)
                #pragma unroll
                for (int j = 0; j < 4; j++)
                    acc[i][j] += a[i] * b[j];
        }
        __syncthreads();
    }

    #pragma unroll
    for (int i = 0; i < 4; i++) {
        float* dst = &g_o[(bh * S + row0 + ty * 4 + i) * DK + tx * 4];
        *(float4*)dst = *(float4*)&acc[i][0];
    }
}

// ---------------- output projection: proj = O @ wo + bo ----------------
__global__ __launch_bounds__(256) void oproj_kernel(
    const float* __restrict__ wo, const float* __restrict__ bo)
{
    __shared__ __align__(16) float As[8][128];
    __shared__ __align__(16) float Bs[8][128];

    const int row0 = blockIdx.y * 128;
    const int col0 = blockIdx.x * 128;
    const int tid = threadIdx.x;
    const int tx = tid & 15, ty = tid >> 4;

    float acc[8][8] = {};

    for (int k0 = 0; k0 < D; k0 += 8) {
        {
            int r = tid >> 1, kk = (tid & 1) * 4;
            int n = row0 + r, b = n >> 11, s = n & (S - 1);
            int c = k0 + kk, h = c >> 6, dk = c & 63;
            float4 a = *(const float4*)&g_o[((b * H + h) * S + s) * DK + dk];
            As[kk + 0][r] = a.x; As[kk + 1][r] = a.y;
            As[kk + 2][r] = a.z; As[kk + 3][r] = a.w;
        }
        {
            int kk = tid >> 5, c = (tid & 31) * 4;
            *(float4*)&Bs[kk][c] = *(const float4*)&wo[(k0 + kk) * D + col0 + c];
        }
        __syncthreads();
        #pragma unroll
        for (int kk = 0; kk < 8; kk++) {
            float a[8], b[8];
            *(float4*)&a[0] = *(float4*)&As[kk][ty * 8];
            *(float4*)&a[4] = *(float4*)&As[kk][ty * 8 + 4];
            *(float4*)&b[0] = *(float4*)&Bs[kk][tx * 8];
            *(float4*)&b[4] = *(float4*)&Bs[kk][tx * 8 + 4];
            #pragma unroll
            for (int i = 0; i < 8; i++)
                #pragma unroll
                for (int j = 0; j < 8; j++)
                    acc[i][j] += a[i] * b[j];
        }
        __syncthreads();
    }

    #pragma unroll
    for (int i = 0; i < 8; i++) {
        int n = row0 + ty * 8 + i;
        int d0 = col0 + tx * 8;
        float v[8];
        #pragma unroll
        for (int j = 0; j < 8; j++) v[j] = acc[i][j] + bo[d0 + j];
        float* dst = &g_proj[n * D + d0];
        *(float4*)&dst[0] = *(float4*)&v[0];
        *(float4*)&dst[4] = *(float4*)&v[4];
    }
}

// ---------------- gate hidden: h = relu(x @ g1_w + g1_b), N=256 ----------------
__global__ __launch_bounds__(256) void hidden_kernel(
    const float* __restrict__ x,
    const float* __restrict__ g1w, const float* __restrict__ g1b)
{
    __shared__ __align__(16) float As[8][128];
    __shared__ __align__(16) float Bs[8][128];

    const int row0 = blockIdx.y * 128;
    const int col0 = blockIdx.x * 128;
    const int tid = threadIdx.x;
    const int tx = tid & 15, ty = tid >> 4;

    float acc[8][8] = {};

    for (int k0 = 0; k0 < D; k0 += 8) {
        {
            int r = tid >> 1, kk = (tid & 1) * 4;
            float4 a = *(const float4*)&x[(row0 + r) * D + k0 + kk];
            As[kk + 0][r] = a.x; As[kk + 1][r] = a.y;
            As[kk + 2][r] = a.z; As[kk + 3][r] = a.w;
        }
        {
            int kk = tid >> 5, c = (tid & 31) * 4;
            *(float4*)&Bs[kk][c] = *(const float4*)&g1w[(k0 + kk) * DH + col0 + c];
        }
        __syncthreads();
        #pragma unroll
        for (int kk = 0; kk < 8; kk++) {
            float a[8], b[8];
            *(float4*)&a[0] = *(float4*)&As[kk][ty * 8];
            *(float4*)&a[4] = *(float4*)&As[kk][ty * 8 + 4];
            *(float4*)&b[0] = *(float4*)&Bs[kk][tx * 8];
            *(float4*)&b[4] = *(float4*)&Bs[kk][tx * 8 + 4];
            #pragma unroll
            for (int i = 0; i < 8; i++)
                #pragma unroll
                for (int j = 0; j < 8; j++)
                    acc[i][j] += a[i] * b[j];
        }
        __syncthreads();
    }

    #pragma unroll
    for (int i = 0; i < 8; i++) {
        int n = row0 + ty * 8 + i;
        int c0 = col0 + tx * 8;
        float v[8];
        #pragma unroll
        for (int j = 0; j < 8; j++) v[j] = fmaxf(acc[i][j] + g1b[c0 + j], 0.0f);
        float* dst = &g_hidden[n * DH + c0];
        *(float4*)&dst[0] = *(float4*)&v[0];
        *(float4*)&dst[4] = *(float4*)&v[4];
    }
}

// ---------------- gate scalar: sigmoid(h @ g2_w + g2_b) ----------------
__global__ void gate_kernel(const float* __restrict__ g2w,
                            const float* __restrict__ g2b)
{
    int warp = (blockIdx.x * blockDim.x + threadIdx.x) >> 5;
    int lane = threadIdx.x & 31;
    if (warp >= NB) return;
    float sum = 0.0f;
    #pragma unroll
    for (int i = 0; i < DH / 32; i++)
        sum += g_hidden[warp * DH + i * 32 + lane] * g2w[i * 32 + lane];
    #pragma unroll
    for (int off = 16; off; off >>= 1)
        sum += __shfl_down_sync(0xffffffffu, sum, off);
    if (lane == 0)
        g_gate[warp] = 1.0f / (1.0f + expf(-(sum + g2b[0])));
}

// ---------------- gated residual + LayerNorm ----------------
__global__ __launch_bounds__(256) void ln_kernel(
    const float* __restrict__ x,
    const float* __restrict__ lng, const float* __restrict__ lnb,
    float* __restrict__ y)
{
    __shared__ float s1[8], s2[8];
    const int n = blockIdx.x;
    const int tid = threadIdx.x;
    const float g = g_gate[n];

    int j0 = tid * 2;
    float2 pr = *(const float2*)&g_proj[n * D + j0];
    float2 xr = *(const float2*)&x[n * D + j0];
    float o0 = pr.x * g + xr.x * (1.0f - g);
    float o1 = pr.y * g + xr.y * (1.0f - g);

    float sum = o0 + o1, sq = o0 * o0 + o1 * o1;
    #pragma unroll
    for (int off = 16; off; off >>= 1) {
        sum += __shfl_down_sync(0xffffffffu, sum, off);
        sq  += __shfl_down_sync(0xffffffffu, sq,  off);
    }
    int wid = tid >> 5, lane = tid & 31;
    if (lane == 0) { s1[wid] = sum; s2[wid] = sq; }
    __syncthreads();
    if (tid == 0) {
        float a = 0.0f, b2 = 0.0f;
        #pragma unroll
        for (int w = 0; w < 8; w++) { a += s1[w]; b2 += s2[w]; }
        s1[0] = a; s2[0] = b2;
    }
    __syncthreads();
    float mean = s1[0] * (1.0f / D);
    float var  = s2[0] * (1.0f / D) - mean * mean;
    float inv  = rsqrtf(var + LN_EPS);
    y[n * D + j0]     = (o0 - mean) * inv * lng[j0]     + lnb[j0];
    y[n * D + j0 + 1] = (o1 - mean) * inv * lng[j0 + 1] + lnb[j0 + 1];
}

// ---------------- launch ----------------
extern "C" void kernel_launch(void* const* d_in, const int* in_sizes, int n_in,
                              void* d_out, int out_size)
{
    (void)in_sizes; (void)n_in; (void)out_size;
    const float* x   = (const float*)d_in[0];
    const float* wq  = (const float*)d_in[1];
    const float* bq  = (const float*)d_in[2];
    const float* wk  = (const float*)d_in[3];
    const float* bk  = (const float*)d_in[4];
    const float* wv  = (const float*)d_in[5];
    const float* bv  = (const float*)d_in[6];
    const float* wo  = (const float*)d_in[7];
    const float* bo  = (const float*)d_in[8];
    const float* g1w = (const float*)d_in[9];
    const float* g1b = (const float*)d_in[10];
    const float* g2w = (const float*)d_in[11];
    const float* g2b = (const float*)d_in[12];
    const float* lng = (const float*)d_in[13];
    const float* lnb = (const float*)d_in[14];
    (void)g1b;

    float* y    = (float*)d_out;
    float* attn = y + (size_t)NB * D;

    const int SMEM_SCORES = (2 * 64 * 128 + 128) * sizeof(float);
    cudaFuncSetAttribute(scores_kernel,
                         cudaFuncAttributeMaxDynamicSharedMemorySize, SMEM_SCORES);

    init_kernel<<<(BH * S + 255) / 256, 256>>>();
    qkv_kernel<<<dim3(D / 128, NB / 128, 3), 256>>>(x, wq, bq, wk, bk, wv, bv);
    scores_kernel<<<dim3(S / 128, S / 128, BH), 256, SMEM_SCORES>>>(attn);
    attnv_kernel<<<dim3(S / 64, BH), 256>>>(attn);
    oproj_kernel<<<dim3(D / 128, NB / 128), 256>>>(wo, bo);
    hidden_kernel<<<dim3(DH / 128, NB / 128), 256>>>(x, g1w, g1b);
    gate_kernel<<<(NB * 32) / 256, 256>>>(g2w, g2b);
    ln_kernel<<<NB, 256>>>(x, lng, lnb, y);
}

// round 4
// speedup vs baseline: 1.3240x; 1.3240x over previous
#include <cuda_runtime.h>
#include <math.h>

// ---------------- problem constants ----------------
namespace {
constexpr int B  = 2;
constexpr int S  = 2048;
constexpr int D  = 512;
constexpr int H  = 8;
constexpr int DK = 64;
constexpr int NB = B * S;     // 4096 tokens
constexpr int BH = B * H;     // 16 (b,h) pairs
constexpr int DH = D / 2;     // 256 gate hidden
constexpr float DECAY = 0.02f;
constexpr float LN_EPS = 1e-5f;
}

// ---------------- device scratch ----------------
__device__ float g_q[BH * S * DK];      // (b,h,s,dk)
__device__ float g_k[BH * S * DK];
__device__ float g_v[BH * S * DK];
__device__ float g_o[BH * S * DK];
__device__ float g_proj[NB * D];
__device__ float g_hidden[NB * DH];
__device__ float g_gate[NB];
__device__ float g_rowsum[BH * S];
__device__ float g_decay[S];

// ---------------- tf32 mma helpers ----------------
__device__ __forceinline__ unsigned cvt_tf32(float f) {
    unsigned u;
    asm("cvt.rna.tf32.f32 %0, %1;" : "=r"(u) : "f"(f));
    return u;
}
__device__ __forceinline__ void split_tf32(float a, unsigned &hi, unsigned &lo) {
    hi = cvt_tf32(a);
    lo = cvt_tf32(a - __uint_as_float(hi));
}
__device__ __forceinline__ void mma8(float (&c)[4], const unsigned (&a)[4],
                                     const unsigned (&b)[2]) {
    asm volatile(
        "mma.sync.aligned.m16n8k8.row.col.f32.tf32.tf32.f32 "
        "{%0,%1,%2,%3}, {%4,%5,%6,%7}, {%8,%9}, {%0,%1,%2,%3};"
        : "+f"(c[0]), "+f"(c[1]), "+f"(c[2]), "+f"(c[3])
        : "r"(a[0]), "r"(a[1]), "r"(a[2]), "r"(a[3]), "r"(b[0]), "r"(b[1]));
}

// ---------------- init ----------------
__global__ void init_kernel() {
    int idx = blockIdx.x * blockDim.x + threadIdx.x;
    if (idx < BH * S) g_rowsum[idx] = 0.0f;
    if (idx < S)      g_decay[idx] = expf(-DECAY * (float)idx);
}

// ---------------- QKV projection GEMM (fp32 FFMA) ----------------
__global__ __launch_bounds__(256) void qkv_kernel(
    const float* __restrict__ x,
    const float* __restrict__ wq, const float* __restrict__ bq,
    const float* __restrict__ wk, const float* __restrict__ bk,
    const float* __restrict__ wv, const float* __restrict__ bv)
{
    __shared__ __align__(16) float As[8][128];
    __shared__ __align__(16) float Bs[8][128];

    const float* W; const float* bias; float* out;
    if (blockIdx.z == 0)      { W = wq; bias = bq; out = g_q; }
    else if (blockIdx.z == 1) { W = wk; bias = bk; out = g_k; }
    else                      { W = wv; bias = bv; out = g_v; }

    const int row0 = blockIdx.y * 128;
    const int col0 = blockIdx.x * 128;
    const int tid = threadIdx.x;
    const int tx = tid & 15, ty = tid >> 4;

    float acc[8][8] = {};

    for (int k0 = 0; k0 < D; k0 += 8) {
        {
            int r = tid >> 1, kk = (tid & 1) * 4;
            float4 a = *(const float4*)&x[(row0 + r) * D + k0 + kk];
            As[kk + 0][r] = a.x; As[kk + 1][r] = a.y;
            As[kk + 2][r] = a.z; As[kk + 3][r] = a.w;
        }
        {
            int kk = tid >> 5, c = (tid & 31) * 4;
            *(float4*)&Bs[kk][c] = *(const float4*)&W[(k0 + kk) * D + col0 + c];
        }
        __syncthreads();
        #pragma unroll
        for (int kk = 0; kk < 8; kk++) {
            float a[8], b[8];
            *(float4*)&a[0] = *(float4*)&As[kk][ty * 8];
            *(float4*)&a[4] = *(float4*)&As[kk][ty * 8 + 4];
            *(float4*)&b[0] = *(float4*)&Bs[kk][tx * 8];
            *(float4*)&b[4] = *(float4*)&Bs[kk][tx * 8 + 4];
            #pragma unroll
            for (int i = 0; i < 8; i++)
                #pragma unroll
                for (int j = 0; j < 8; j++)
                    acc[i][j] += a[i] * b[j];
        }
        __syncthreads();
    }

    #pragma unroll
    for (int i = 0; i < 8; i++) {
        int n = row0 + ty * 8 + i;
        int b = n >> 11, s = n & (S - 1);
        int d0 = col0 + tx * 8;
        int h = d0 >> 6, dk = d0 & 63;
        float v[8];
        #pragma unroll
        for (int j = 0; j < 8; j++) v[j] = acc[i][j] + bias[d0 + j];
        float* dst = &out[((b * H + h) * S + s) * DK + dk];
        *(float4*)&dst[0] = *(float4*)&v[0];
        *(float4*)&dst[4] = *(float4*)&v[4];
    }
}

// ---------------- scores via tf32 mma: P = exp(QK^T/8 + bias) ----------------
// Block = 128q x 128k tile, one (b,h). 8 warps as 4(m) x 2(n); warp tile 32x64.
// Smem: Qs[128][68] + Ks[128][68] + ssum[128] = 70144 B. Stride 68 -> conflict-free frags.
__global__ __launch_bounds__(256) void scores_kernel(float* __restrict__ attn)
{
    extern __shared__ __align__(16) float smem[];
    float* Qs = smem;                 // [128][68]
    float* Ks = smem + 128 * 68;      // [128][68]
    float* ssum = smem + 2 * 128 * 68;

    const int bh = blockIdx.z;
    const int row0 = blockIdx.y * 128;
    const int col0 = blockIdx.x * 128;
    const int tid = threadIdx.x;
    const int lane = tid & 31, wid = tid >> 5;
    const int g = lane >> 2, t4 = lane & 3;
    const int wm = wid >> 1, wn = wid & 1;

    const float* qb = g_q + ((size_t)bh * S + row0) * DK;
    const float* kb = g_k + ((size_t)bh * S + col0) * DK;

    #pragma unroll
    for (int i = 0; i < 8; i++) {
        int lin = i * 256 + tid;
        int r = lin >> 4, c4 = (lin & 15) * 4;
        *(float4*)&Qs[r * 68 + c4] = *(const float4*)&qb[r * DK + c4];
        *(float4*)&Ks[r * 68 + c4] = *(const float4*)&kb[r * DK + c4];
    }
    if (tid < 128) ssum[tid] = 0.0f;
    __syncthreads();

    float acc[2][8][4] = {};

    #pragma unroll
    for (int ks = 0; ks < 8; ks++) {
        const int k0 = ks * 8;
        unsigned ahi[2][4], alo[2][4], bhi[8][2], blo[8][2];
        #pragma unroll
        for (int mt = 0; mt < 2; mt++) {
            const float* base = Qs + (wm * 32 + mt * 16 + g) * 68 + k0;
            split_tf32(base[t4],              ahi[mt][0], alo[mt][0]);
            split_tf32(base[8 * 68 + t4],     ahi[mt][1], alo[mt][1]);
            split_tf32(base[t4 + 4],          ahi[mt][2], alo[mt][2]);
            split_tf32(base[8 * 68 + t4 + 4], ahi[mt][3], alo[mt][3]);
        }
        #pragma unroll
        for (int nt = 0; nt < 8; nt++) {
            const float* base = Ks + (wn * 64 + nt * 8 + g) * 68 + k0;
            split_tf32(base[t4],     bhi[nt][0], blo[nt][0]);
            split_tf32(base[t4 + 4], bhi[nt][1], blo[nt][1]);
        }
        #pragma unroll
        for (int mt = 0; mt < 2; mt++)
            #pragma unroll
            for (int nt = 0; nt < 8; nt++)
                mma8(acc[mt][nt], ahi[mt], bhi[nt]);
        #pragma unroll
        for (int mt = 0; mt < 2; mt++)
            #pragma unroll
            for (int nt = 0; nt < 8; nt++)
                mma8(acc[mt][nt], alo[mt], bhi[nt]);
        #pragma unroll
        for (int mt = 0; mt < 2; mt++)
            #pragma unroll
            for (int nt = 0; nt < 8; nt++)
                mma8(acc[mt][nt], ahi[mt], blo[nt]);
    }

    // epilogue: exp + bias, rowsum, store
    float rsum[2][2] = {};
    #pragma unroll
    for (int mt = 0; mt < 2; mt++) {
        int rl = wm * 32 + mt * 16 + g;
        int gi0 = row0 + rl, gi1 = gi0 + 8;
        #pragma unroll
        for (int nt = 0; nt < 8; nt++) {
            int gj = col0 + wn * 64 + nt * 8 + 2 * t4;
            float p[4];
            #pragma unroll
            for (int e = 0; e < 4; e++) {
                int gi = (e < 2) ? gi0 : gi1;
                int gje = gj + (e & 1);
                float v = acc[mt][nt][e] * 0.125f;
                int dist = gi - gje;
                if (dist >= 0) v += g_decay[dist];
                p[e] = __expf(v);
            }
            rsum[mt][0] += p[0] + p[1];
            rsum[mt][1] += p[2] + p[3];
            *(float2*)(attn + ((size_t)bh * S + gi0) * S + gj) = make_float2(p[0], p[1]);
            *(float2*)(attn + ((size_t)bh * S + gi1) * S + gj) = make_float2(p[2], p[3]);
        }
    }
    #pragma unroll
    for (int mt = 0; mt < 2; mt++)
        #pragma unroll
        for (int h2 = 0; h2 < 2; h2++) {
            float v = rsum[mt][h2];
            v += __shfl_xor_sync(0xffffffffu, v, 1);
            v += __shfl_xor_sync(0xffffffffu, v, 2);
            if (t4 == 0) atomicAdd(&ssum[wm * 32 + mt * 16 + h2 * 8 + g], v);
        }
    __syncthreads();
    if (tid < 128) atomicAdd(&g_rowsum[(size_t)bh * S + row0 + tid], ssum[tid]);
}

// ---------------- attn@V via tf32 mma + in-place normalization ----------------
// Block = 128q x 64(DK), loop keys in 64-chunks. 8 warps as 4(m) x 2(n); warp 32x32.
// Smem: Ps[128][68] + Vs[64][72] + srow[128] = 53760 B.
__global__ __launch_bounds__(256) void attnv_kernel(float* __restrict__ attn)
{
    extern __shared__ __align__(16) float smem[];
    float* Ps = smem;                      // [128][68]
    float* Vs = smem + 128 * 68;           // [64][72]
    float* srow = Vs + 64 * 72;            // [128]

    const int bh = blockIdx.y;
    const int row0 = blockIdx.x * 128;
    const int tid = threadIdx.x;
    const int lane = tid & 31, wid = tid >> 5;
    const int g = lane >> 2, t4 = lane & 3;
    const int wm = wid >> 1, wn = wid & 1;

    if (tid < 128) srow[tid] = 1.0f / g_rowsum[(size_t)bh * S + row0 + tid];
    __syncthreads();

    float acc[2][4][4] = {};

    for (int k0 = 0; k0 < S; k0 += 64) {
        // load P tile 128x64, normalize, write back, stage
        #pragma unroll
        for (int i = 0; i < 8; i++) {
            int lin = i * 256 + tid;
            int r = lin >> 4, c4 = (lin & 15) * 4;
            float* gp = attn + ((size_t)bh * S + row0 + r) * S + k0 + c4;
            float4 a = *(const float4*)gp;
            float inv = srow[r];
            a.x *= inv; a.y *= inv; a.z *= inv; a.w *= inv;
            *(float4*)gp = a;
            *(float4*)&Ps[r * 68 + c4] = a;
        }
        // load V tile 64x64
        #pragma unroll
        for (int i = 0; i < 4; i++) {
            int lin = i * 256 + tid;
            int r = lin >> 4, c4 = (lin & 15) * 4;
            *(float4*)&Vs[r * 72 + c4] =
                *(const float4*)&g_v[((size_t)bh * S + k0 + r) * DK + c4];
        }
        __syncthreads();

        #pragma unroll
        for (int ks = 0; ks < 8; ks++) {
            const int kk = ks * 8;
            unsigned ahi[2][4], alo[2][4], bhi[4][2], blo[4][2];
            #pragma unroll
            for (int mt = 0; mt < 2; mt++) {
                const float* base = Ps + (wm * 32 + mt * 16 + g) * 68 + kk;
                split_tf32(base[t4],              ahi[mt][0], alo[mt][0]);
                split_tf32(base[8 * 68 + t4],     ahi[mt][1], alo[mt][1]);
                split_tf32(base[t4 + 4],          ahi[mt][2], alo[mt][2]);
                split_tf32(base[8 * 68 + t4 + 4], ahi[mt][3], alo[mt][3]);
            }
            #pragma unroll
            for (int nt = 0; nt < 4; nt++) {
                int n = wn * 32 + nt * 8 + g;
                split_tf32(Vs[(kk + t4) * 72 + n],     bhi[nt][0], blo[nt][0]);
                split_tf32(Vs[(kk + t4 + 4) * 72 + n], bhi[nt][1], blo[nt][1]);
            }
            #pragma unroll
            for (int mt = 0; mt < 2; mt++)
                #pragma unroll
                for (int nt = 0; nt < 4; nt++)
                    mma8(acc[mt][nt], ahi[mt], bhi[nt]);
            #pragma unroll
            for (int mt = 0; mt < 2; mt++)
                #pragma unroll
                for (int nt = 0; nt < 4; nt++)
                    mma8(acc[mt][nt], alo[mt], bhi[nt]);
            #pragma unroll
            for (int mt = 0; mt < 2; mt++)
                #pragma unroll
                for (int nt = 0; nt < 4; nt++)
                    mma8(acc[mt][nt], ahi[mt], blo[nt]);
        }
        __syncthreads();
    }

    #pragma unroll
    for (int mt = 0; mt < 2; mt++) {
        int rl = wm * 32 + mt * 16 + g;
        #pragma unroll
        for (int nt = 0; nt < 4; nt++) {
            int col = wn * 32 + nt * 8 + 2 * t4;
            *(float2*)&g_o[((size_t)bh * S + row0 + rl) * DK + col] =
                make_float2(acc[mt][nt][0], acc[mt][nt][1]);
            *(float2*)&g_o[((size_t)bh * S + row0 + rl + 8) * DK + col] =
                make_float2(acc[mt][nt][2], acc[mt][nt][3]);
        }
    }
}

// ---------------- output projection: proj = O @ wo + bo ----------------
__global__ __launch_bounds__(256) void oproj_kernel(
    const float* __restrict__ wo, const float* __restrict__ bo)
{
    __shared__ __align__(16) float As[8][128];
    __shared__ __align__(16) float Bs[8][128];

    const int row0 = blockIdx.y * 128;
    const int col0 = blockIdx.x * 128;
    const int tid = threadIdx.x;
    const int tx = tid & 15, ty = tid >> 4;

    float acc[8][8] = {};

    for (int k0 = 0; k0 < D; k0 += 8) {
        {
            int r = tid >> 1, kk = (tid & 1) * 4;
            int n = row0 + r, b = n >> 11, s = n & (S - 1);
            int c = k0 + kk, h = c >> 6, dk = c & 63;
            float4 a = *(const float4*)&g_o[((b * H + h) * S + s) * DK + dk];
            As[kk + 0][r] = a.x; As[kk + 1][r] = a.y;
            As[kk + 2][r] = a.z; As[kk + 3][r] = a.w;
        }
        {
            int kk = tid >> 5, c = (tid & 31) * 4;
            *(float4*)&Bs[kk][c] = *(const float4*)&wo[(k0 + kk) * D + col0 + c];
        }
        __syncthreads();
        #pragma unroll
        for (int kk = 0; kk < 8; kk++) {
            float a[8], b[8];
            *(float4*)&a[0] = *(float4*)&As[kk][ty * 8];
            *(float4*)&a[4] = *(float4*)&As[kk][ty * 8 + 4];
            *(float4*)&b[0] = *(float4*)&Bs[kk][tx * 8];
            *(float4*)&b[4] = *(float4*)&Bs[kk][tx * 8 + 4];
            #pragma unroll
            for (int i = 0; i < 8; i++)
                #pragma unroll
                for (int j = 0; j < 8; j++)
                    acc[i][j] += a[i] * b[j];
        }
        __syncthreads();
    }

    #pragma unroll
    for (int i = 0; i < 8; i++) {
        int n = row0 + ty * 8 + i;
        int d0 = col0 + tx * 8;
        float v[8];
        #pragma unroll
        for (int j = 0; j < 8; j++) v[j] = acc[i][j] + bo[d0 + j];
        float* dst = &g_proj[n * D + d0];
        *(float4*)&dst[0] = *(float4*)&v[0];
        *(float4*)&dst[4] = *(float4*)&v[4];
    }
}

// ---------------- gate hidden: h = relu(x @ g1_w + g1_b) ----------------
__global__ __launch_bounds__(256) void hidden_kernel(
    const float* __restrict__ x,
    const float* __restrict__ g1w, const float* __restrict__ g1b)
{
    __shared__ __align__(16) float As[8][128];
    __shared__ __align__(16) float Bs[8][128];

    const int row0 = blockIdx.y * 128;
    const int col0 = blockIdx.x * 128;
    const int tid = threadIdx.x;
    const int tx = tid & 15, ty = tid >> 4;

    float acc[8][8] = {};

    for (int k0 = 0; k0 < D; k0 += 8) {
        {
            int r = tid >> 1, kk = (tid & 1) * 4;
            float4 a = *(const float4*)&x[(row0 + r) * D + k0 + kk];
            As[kk + 0][r] = a.x; As[kk + 1][r] = a.y;
            As[kk + 2][r] = a.z; As[kk + 3][r] = a.w;
        }
        {
            int kk = tid >> 5, c = (tid & 31) * 4;
            *(float4*)&Bs[kk][c] = *(const float4*)&g1w[(k0 + kk) * DH + col0 + c];
        }
        __syncthreads();
        #pragma unroll
        for (int kk = 0; kk < 8; kk++) {
            float a[8], b[8];
            *(float4*)&a[0] = *(float4*)&As[kk][ty * 8];
            *(float4*)&a[4] = *(float4*)&As[kk][ty * 8 + 4];
            *(float4*)&b[0] = *(float4*)&Bs[kk][tx * 8];
            *(float4*)&b[4] = *(float4*)&Bs[kk][tx * 8 + 4];
            #pragma unroll
            for (int i = 0; i < 8; i++)
                #pragma unroll
                for (int j = 0; j < 8; j++)
                    acc[i][j] += a[i] * b[j];
        }
        __syncthreads();
    }

    #pragma unroll
    for (int i = 0; i < 8; i++) {
        int n = row0 + ty * 8 + i;
        int c0 = col0 + tx * 8;
        float v[8];
        #pragma unroll
        for (int j = 0; j < 8; j++) v[j] = fmaxf(acc[i][j] + g1b[c0 + j], 0.0f);
        float* dst = &g_hidden[n * DH + c0];
        *(float4*)&dst[0] = *(float4*)&v[0];
        *(float4*)&dst[4] = *(float4*)&v[4];
    }
}

// ---------------- gate scalar: sigmoid(h @ g2_w + g2_b) ----------------
__global__ void gate_kernel(const float* __restrict__ g2w,
                            const float* __restrict__ g2b)
{
    int warp = (blockIdx.x * blockDim.x + threadIdx.x) >> 5;
    int lane = threadIdx.x & 31;
    if (warp >= NB) return;
    float sum = 0.0f;
    #pragma unroll
    for (int i = 0; i < DH / 32; i++)
        sum += g_hidden[warp * DH + i * 32 + lane] * g2w[i * 32 + lane];
    #pragma unroll
    for (int off = 16; off; off >>= 1)
        sum += __shfl_down_sync(0xffffffffu, sum, off);
    if (lane == 0)
        g_gate[warp] = 1.0f / (1.0f + expf(-(sum + g2b[0])));
}

// ---------------- gated residual + LayerNorm ----------------
__global__ __launch_bounds__(256) void ln_kernel(
    const float* __restrict__ x,
    const float* __restrict__ lng, const float* __restrict__ lnb,
    float* __restrict__ y)
{
    __shared__ float s1[8], s2[8];
    const int n = blockIdx.x;
    const int tid = threadIdx.x;
    const float g = g_gate[n];

    int j0 = tid * 2;
    float2 pr = *(const float2*)&g_proj[n * D + j0];
    float2 xr = *(const float2*)&x[n * D + j0];
    float o0 = pr.x * g + xr.x * (1.0f - g);
    float o1 = pr.y * g + xr.y * (1.0f - g);

    float sum = o0 + o1, sq = o0 * o0 + o1 * o1;
    #pragma unroll
    for (int off = 16; off; off >>= 1) {
        sum += __shfl_down_sync(0xffffffffu, sum, off);
        sq  += __shfl_down_sync(0xffffffffu, sq,  off);
    }
    int wid = tid >> 5, lane = tid & 31;
    if (lane == 0) { s1[wid] = sum; s2[wid] = sq; }
    __syncthreads();
    if (tid == 0) {
        float a = 0.0f, b2 = 0.0f;
        #pragma unroll
        for (int w = 0; w < 8; w++) { a += s1[w]; b2 += s2[w]; }
        s1[0] = a; s2[0] = b2;
    }
    __syncthreads();
    float mean = s1[0] * (1.0f / D);
    float var  = s2[0] * (1.0f / D) - mean * mean;
    float inv  = rsqrtf(var + LN_EPS);
    y[n * D + j0]     = (o0 - mean) * inv * lng[j0]     + lnb[j0];
    y[n * D + j0 + 1] = (o1 - mean) * inv * lng[j0 + 1] + lnb[j0 + 1];
}

// ---------------- launch ----------------
extern "C" void kernel_launch(void* const* d_in, const int* in_sizes, int n_in,
                              void* d_out, int out_size)
{
    (void)in_sizes; (void)n_in; (void)out_size;
    const float* x   = (const float*)d_in[0];
    const float* wq  = (const float*)d_in[1];
    const float* bq  = (const float*)d_in[2];
    const float* wk  = (const float*)d_in[3];
    const float* bk  = (const float*)d_in[4];
    const float* wv  = (const float*)d_in[5];
    const float* bv  = (const float*)d_in[6];
    const float* wo  = (const float*)d_in[7];
    const float* bo  = (const float*)d_in[8];
    const float* g1w = (const float*)d_in[9];
    const float* g1b = (const float*)d_in[10];
    const float* g2w = (const float*)d_in[11];
    const float* g2b = (const float*)d_in[12];
    const float* lng = (const float*)d_in[13];
    const float* lnb = (const float*)d_in[14];

    float* y    = (float*)d_out;
    float* attn = y + (size_t)NB * D;

    const int SMEM_SCORES = (2 * 128 * 68 + 128) * (int)sizeof(float);   // 70144
    const int SMEM_ATTNV  = (128 * 68 + 64 * 72 + 128) * (int)sizeof(float); // 53760
    cudaFuncSetAttribute(scores_kernel,
                         cudaFuncAttributeMaxDynamicSharedMemorySize, SMEM_SCORES);
    cudaFuncSetAttribute(attnv_kernel,
                         cudaFuncAttributeMaxDynamicSharedMemorySize, SMEM_ATTNV);

    init_kernel<<<(BH * S + 255) / 256, 256>>>();
    qkv_kernel<<<dim3(D / 128, NB / 128, 3), 256>>>(x, wq, bq, wk, bk, wv, bv);
    scores_kernel<<<dim3(S / 128, S / 128, BH), 256, SMEM_SCORES>>>(attn);
    attnv_kernel<<<dim3(S / 128, BH), 256, SMEM_ATTNV>>>(attn);
    oproj_kernel<<<dim3(D / 128, NB / 128), 256>>>(wo, bo);
    hidden_kernel<<<dim3(DH / 128, NB / 128), 256>>>(x, g1w, g1b);
    gate_kernel<<<(NB * 32) / 256, 256>>>(g2w, g2b);
    ln_kernel<<<NB, 256>>>(x, lng, lnb, y);
}